// round 11
// baseline (speedup 1.0000x reference)
#include <cuda_runtime.h>

// RNNModel: h_t = tanh(x_t @ W_ih^T + b_ih + h_{t-1} @ W_hh^T + b_hh); out = h_T @ fc_W^T + fc_b
// B=4096, T=512, D_IN=8, H=50, D_OUT=1
//
// R11: two warps per batch, ONE hidden unit per lane.
//   R6 kept 2 units/lane -> 116 W regs -> 166 total -> only 2.6 warps/SMSP; warps
//   slept ~700 cyc/step. Splitting a batch across a 2-warp (64-thread) block
//   halves W to 58 regs/thread (~100 total) -> 10 blocks/SM -> 5 warps/SMSP,
//   same total FFMA2 warp-instructions (29/warp-step). h is shared through the
//   block with one cheap 2-warp __syncthreads per step. x is register-prefetched
//   one step ahead + prefetch.global.L2 eight steps ahead, so no demand-miss sits
//   at the head of the per-step dependency chain.

#define B_SZ 4096
#define T_SZ 512
#define DIN  8
#define H_SZ 50
#define NTHR 64                   // 2 warps = 1 batch

typedef unsigned long long ull;

__device__ __forceinline__ ull pack2(float lo, float hi) {
    ull r; asm("mov.b64 %0, {%1, %2};" : "=l"(r) : "f"(lo), "f"(hi)); return r;
}
__device__ __forceinline__ void unpack2(ull v, float& lo, float& hi) {
    asm("mov.b64 {%0, %1}, %2;" : "=f"(lo), "=f"(hi) : "l"(v));
}
__device__ __forceinline__ ull fma2(ull a, ull b, ull c) {
    ull r; asm("fma.rn.f32x2 %0, %1, %2, %3;" : "=l"(r) : "l"(a), "l"(b), "l"(c)); return r;
}
__device__ __forceinline__ ull add2(ull a, ull b) {
    ull r; asm("add.rn.f32x2 %0, %1, %2;" : "=l"(r) : "l"(a), "l"(b)); return r;
}
__device__ __forceinline__ float tanh_fast(float v) {
    // tanh(v) = 1 - 2/(exp(2v)+1); robust at extremes, ~1e-7 rel err
    float e = __expf(2.0f * v);
    return 1.0f - __fdividef(2.0f, e + 1.0f);
}

__global__ void __launch_bounds__(NTHR, 10)
rnn_kernel(const float* __restrict__ x,
           const float* __restrict__ Wih,
           const float* __restrict__ Whh,
           const float* __restrict__ bih,
           const float* __restrict__ bhh,
           const float* __restrict__ fcW,
           const float* __restrict__ fcb,
           float* __restrict__ out)
{
    // plain h, double buffered, padded to 64 floats. 2 * 64 * 4B = 512 B
    __shared__ float hb[2][64];
    __shared__ float red[2];                  // fc cross-warp partials

    const int tid   = threadIdx.x;
    const int whalf = tid >> 5;               // 0 or 1: which 25-unit half
    const int lane  = tid & 31;
    const int b     = blockIdx.x;

    // unit owned by this lane; pad lanes (25..31) clamp to a valid row and
    // write to scratch slots so the loop body is branch-free.
    const int j    = whalf * 25 + ((lane < 25) ? lane : 24);   // clamped row
    const int slot = (lane < 25) ? (whalf * 25 + lane)
                                 : (50 + whalf * 7 + (lane - 25));

    // W pairs in registers: 25 Whh k-pairs + 4 Wih d-pairs = 29 ull = 58 regs
    ull W[29];
#pragma unroll
    for (int q = 0; q < 25; q++)
        W[q] = pack2(Whh[j * H_SZ + 2 * q], Whh[j * H_SZ + 2 * q + 1]);
#pragma unroll
    for (int d = 0; d < 4; d++)
        W[25 + d] = pack2(Wih[j * DIN + 2 * d], Wih[j * DIN + 2 * d + 1]);
    const ull bp = pack2(bih[j] + bhh[j], 0.0f);   // bias rides the even chain

    // zero both buffers (h0 = 0; pad slots must stay finite)
#pragma unroll
    for (int i = tid; i < 2 * 64; i += NTHR)
        (&hb[0][0])[i] = 0.0f;
    __syncthreads();

    // x row for this batch as packed pairs (16B-aligned: b*T*DIN*4 = b*16KB)
    const ulonglong2* __restrict__ xq =
        (const ulonglong2*)(x + (size_t)b * T_SZ * DIN);

    ulonglong2 xA = xq[0];                    // x_0, register-prefetched
    ulonglong2 xB = xq[1];

    float* cbuf = hb[0];
    float* nbuf = hb[1];
    float  v    = 0.f;

#pragma unroll 1
    for (int t = 0; t < T_SZ; t++) {
        // prefetch x_{t+1} into regs; far prefetch to L2 (no registers)
        const int tn = (t < T_SZ - 1) ? t + 1 : T_SZ - 1;
        ulonglong2 nA = xq[2 * tn];
        ulonglong2 nB = xq[2 * tn + 1];
        const int tf = (t + 8 < T_SZ) ? t + 8 : T_SZ - 1;
        asm volatile("prefetch.global.L2 [%0];" :: "l"(xq + 2 * tf));

        // input projection: two accumulator chains (even-k / odd-k halves)
        ull ax = fma2(xA.x, W[25], bp);
        ull ay = fma2(xA.y, W[26], pack2(0.f, 0.f));
        ax = fma2(xB.x, W[27], ax);
        ay = fma2(xB.y, W[28], ay);

        // recurrence: 12 x broadcast LDS.128 + 1 x LDS.64, 25 FFMA2
        const ulonglong2* __restrict__ hp = (const ulonglong2*)cbuf;
#pragma unroll
        for (int p = 0; p < 12; p++) {
            ulonglong2 hh = hp[p];            // (h4p,h4p+1),(h4p+2,h4p+3)
            ax = fma2(hh.x, W[2 * p],     ax);
            ay = fma2(hh.y, W[2 * p + 1], ay);
        }
        {
            ull h24 = ((const ull*)cbuf)[24]; // (h48,h49)
            ax = fma2(h24, W[24], ax);
        }

        float e, o; unpack2(add2(ax, ay), e, o);
        v = tanh_fast(e + o);

        nbuf[slot] = v;                       // STS.32, conflict-free
        __syncthreads();                      // 2-warp barrier, symmetric arrival

        float* tmp = cbuf; cbuf = nbuf; nbuf = tmp;
        xA = nA; xB = nB;
    }

    // fc readout: out[b] = sum_j h_T[j]*fcW[j] + fcb[0]
    float part = (lane < 25) ? v * fcW[j] : 0.f;
#pragma unroll
    for (int off = 16; off; off >>= 1)
        part += __shfl_down_sync(0xffffffffu, part, off);
    if (lane == 0) red[whalf] = part;
    __syncthreads();
    if (tid == 0)
        out[b] = red[0] + red[1] + fcb[0];
}

extern "C" void kernel_launch(void* const* d_in, const int* in_sizes, int n_in,
                              void* d_out, int out_size)
{
    const float* x   = (const float*)d_in[0];
    const float* Wih = (const float*)d_in[1];
    const float* Whh = (const float*)d_in[2];
    const float* bih = (const float*)d_in[3];
    const float* bhh = (const float*)d_in[4];
    const float* fcW = (const float*)d_in[5];
    const float* fcb = (const float*)d_in[6];
    float* out = (float*)d_out;

    rnn_kernel<<<B_SZ, NTHR>>>(x, Wih, Whh, bih, bhh, fcW, fcb, out);
}

// round 16
// speedup vs baseline: 1.0563x; 1.0563x over previous
#include <cuda_runtime.h>

// RNNModel: h_t = tanh(x_t @ W_ih^T + b_ih + h_{t-1} @ W_hh^T + b_hh); out = h_T @ fc_W^T + fc_b
// B=4096, T=512, D_IN=8, H=50, D_OUT=1
//
// R12: warp-per-TWO-batches, 2 units/lane, k-pair-packed FFMA2.
//   R11 showed cross-warp h sharing saturates L1tex (26 LDS.128/batch-step).
//   Here each warp privately owns TWO batches, reusing its register-resident W
//   (116 regs, batch-invariant) for both -> 8 independent ~25-deep FMA chains
//   per lane; the warp nearly saturates the FMA pipe alone, so 12 warps/SM
//   (3/SMSP) suffice. LDS stays 13/batch-step (R6 level). x is a demand LDG at
//   step top consumed at the chain tail (~150cyc slack) + prefetch.global.L2
//   8 steps ahead. One __syncwarp per step; no cross-warp coupling anywhere.

#define B_SZ 4096
#define T_SZ 512
#define DIN  8
#define H_SZ 50
#define NTHR 64                   // 2 warps/block, each warp = 2 batches

typedef unsigned long long ull;

__device__ __forceinline__ ull pack2(float lo, float hi) {
    ull r; asm("mov.b64 %0, {%1, %2};" : "=l"(r) : "f"(lo), "f"(hi)); return r;
}
__device__ __forceinline__ void unpack2(ull v, float& lo, float& hi) {
    asm("mov.b64 {%0, %1}, %2;" : "=f"(lo), "=f"(hi) : "l"(v));
}
__device__ __forceinline__ ull fma2(ull a, ull b, ull c) {
    ull r; asm("fma.rn.f32x2 %0, %1, %2, %3;" : "=l"(r) : "l"(a), "l"(b), "l"(c)); return r;
}
__device__ __forceinline__ ull add2(ull a, ull b) {
    ull r; asm("add.rn.f32x2 %0, %1, %2;" : "=l"(r) : "l"(a), "l"(b)); return r;
}
__device__ __forceinline__ float tanh_fast(float v) {
    // tanh(v) = 1 - 2/(exp(2v)+1); robust at extremes, ~1e-7 rel err
    float e = __expf(2.0f * v);
    return 1.0f - __fdividef(2.0f, e + 1.0f);
}

__global__ void __launch_bounds__(NTHR, 6)
rnn_kernel(const float* __restrict__ x,
           const float* __restrict__ Wih,
           const float* __restrict__ Whh,
           const float* __restrict__ bih,
           const float* __restrict__ bhh,
           const float* __restrict__ fcW,
           const float* __restrict__ fcb,
           float* __restrict__ out)
{
    // plain h, double buffered, padded to 64 floats. 4 batches * 2 * 64 * 4B = 2 KB
    __shared__ float hb[4][2][64];

    const int tid  = threadIdx.x;
    const int wrp  = tid >> 5;
    const int lane = tid & 31;
    const int lb0  = wrp * 2;                 // this warp's two local batches
    const int lb1  = lb0 + 1;
    const int b0   = blockIdx.x * 4 + lb0;
    const int b1   = b0 + 1;

    // lanes 25..31 clamp to valid rows, write harmless dups into pad slots
    const int j0 = 2 * lane;                  // raw slot (<= 62, within pad)
    const int r0 = (j0     < H_SZ) ? j0     : (H_SZ - 1);
    const int r1 = (j0 + 1 < H_SZ) ? j0 + 1 : (H_SZ - 1);

    // W pairs in registers (batch-invariant, reused for both batches):
    // q<25 from W_hh (cols 2q,2q+1), q=25..28 from W_ih.  2 x 29 ull = 116 regs
    ull W0[29], W1[29];
#pragma unroll
    for (int q = 0; q < 25; q++) {
        W0[q] = pack2(Whh[r0 * H_SZ + 2 * q], Whh[r0 * H_SZ + 2 * q + 1]);
        W1[q] = pack2(Whh[r1 * H_SZ + 2 * q], Whh[r1 * H_SZ + 2 * q + 1]);
    }
#pragma unroll
    for (int d = 0; d < 4; d++) {
        W0[25 + d] = pack2(Wih[r0 * DIN + 2 * d], Wih[r0 * DIN + 2 * d + 1]);
        W1[25 + d] = pack2(Wih[r1 * DIN + 2 * d], Wih[r1 * DIN + 2 * d + 1]);
    }
    const ull b0p = pack2(bih[r0] + bhh[r0], 0.0f);   // bias rides even chain
    const ull b1p = pack2(bih[r1] + bhh[r1], 0.0f);
    const ull z2  = pack2(0.0f, 0.0f);

    // zero all buffers (h0 = 0; pad slots must stay finite)
#pragma unroll
    for (int i = tid; i < 4 * 2 * 64; i += NTHR)
        (&hb[0][0][0])[i] = 0.0f;
    __syncthreads();

    // x rows as packed pairs (16B-aligned: b*T*DIN*4 = b*16KB)
    const ulonglong2* __restrict__ xq0 =
        (const ulonglong2*)(x + (size_t)b0 * T_SZ * DIN);
    const ulonglong2* __restrict__ xq1 =
        (const ulonglong2*)(x + (size_t)b1 * T_SZ * DIN);

    float v00 = 0.f, v01 = 0.f, v10 = 0.f, v11 = 0.f;

#pragma unroll 1
    for (int t = 0; t < T_SZ; t += 2) {
#pragma unroll
        for (int half = 0; half < 2; half++) {
            const int tt  = t + half;
            const int cur = half;             // read buf `half`, write `half^1`

            // demand x loads at step top; consumed only at the chain tail
            const ulonglong2 xA0 = xq0[2 * tt];
            const ulonglong2 xB0 = xq0[2 * tt + 1];
            const ulonglong2 xA1 = xq1[2 * tt];
            const ulonglong2 xB1 = xq1[2 * tt + 1];
            const int tf = (tt + 8 < T_SZ) ? tt + 8 : T_SZ - 1;
            asm volatile("prefetch.global.L2 [%0];" :: "l"(xq0 + 2 * tf));
            asm volatile("prefetch.global.L2 [%0];" :: "l"(xq1 + 2 * tf));

            // 8 accumulator chains: (unit r0/r1) x (batch 0/1) x (even/odd k)
            ull a00x = b0p, a00y = z2;        // batch0 unit r0
            ull a01x = b1p, a01y = z2;        // batch0 unit r1
            ull a10x = b0p, a10y = z2;        // batch1 unit r0
            ull a11x = b1p, a11y = z2;        // batch1 unit r1

            const ulonglong2* __restrict__ hp0 = (const ulonglong2*)hb[lb0][cur];
            const ulonglong2* __restrict__ hp1 = (const ulonglong2*)hb[lb1][cur];
#pragma unroll
            for (int p = 0; p < 12; p++) {
                ulonglong2 g0 = hp0[p];       // batch0: (h4p,h4p+1),(h4p+2,h4p+3)
                ulonglong2 g1 = hp1[p];       // batch1
                a00x = fma2(g0.x, W0[2 * p],     a00x);
                a00y = fma2(g0.y, W0[2 * p + 1], a00y);
                a01x = fma2(g0.x, W1[2 * p],     a01x);
                a01y = fma2(g0.y, W1[2 * p + 1], a01y);
                a10x = fma2(g1.x, W0[2 * p],     a10x);
                a10y = fma2(g1.y, W0[2 * p + 1], a10y);
                a11x = fma2(g1.x, W1[2 * p],     a11x);
                a11y = fma2(g1.y, W1[2 * p + 1], a11y);
            }
            {
                ull h24a = ((const ull*)hb[lb0][cur])[24];  // (h48,h49) b0
                ull h24b = ((const ull*)hb[lb1][cur])[24];  // (h48,h49) b1
                a00x = fma2(h24a, W0[24], a00x);
                a01x = fma2(h24a, W1[24], a01x);
                a10x = fma2(h24b, W0[24], a10x);
                a11x = fma2(h24b, W1[24], a11x);
            }

            // input projection at the tail (x latency covered by recurrence)
            a00x = fma2(xA0.x, W0[25], a00x);  a00y = fma2(xA0.y, W0[26], a00y);
            a01x = fma2(xA0.x, W1[25], a01x);  a01y = fma2(xA0.y, W1[26], a01y);
            a10x = fma2(xA1.x, W0[25], a10x);  a10y = fma2(xA1.y, W0[26], a10y);
            a11x = fma2(xA1.x, W1[25], a11x);  a11y = fma2(xA1.y, W1[26], a11y);
            a00x = fma2(xB0.x, W0[27], a00x);  a00y = fma2(xB0.y, W0[28], a00y);
            a01x = fma2(xB0.x, W1[27], a01x);  a01y = fma2(xB0.y, W1[28], a01y);
            a10x = fma2(xB1.x, W0[27], a10x);  a10y = fma2(xB1.y, W0[28], a10y);
            a11x = fma2(xB1.x, W1[27], a11x);  a11y = fma2(xB1.y, W1[28], a11y);

            float e, o;
            unpack2(add2(a00x, a00y), e, o);  v00 = tanh_fast(e + o);
            unpack2(add2(a01x, a01y), e, o);  v01 = tanh_fast(e + o);
            unpack2(add2(a10x, a10y), e, o);  v10 = tanh_fast(e + o);
            unpack2(add2(a11x, a11y), e, o);  v11 = tanh_fast(e + o);

            *(float2*)&hb[lb0][cur ^ 1][j0] = make_float2(v00, v01);
            *(float2*)&hb[lb1][cur ^ 1][j0] = make_float2(v10, v11);
            __syncwarp();
        }
    }

    // fc readout: out[b] = sum_j h_T[j]*fcW[j] + fcb[0]  (two parallel reductions)
    float p0 = 0.f, p1 = 0.f;
    if (lane < 25) {
        p0 = v00 * fcW[j0] + v01 * fcW[j0 + 1];
        p1 = v10 * fcW[j0] + v11 * fcW[j0 + 1];
    }
#pragma unroll
    for (int off = 16; off; off >>= 1) {
        p0 += __shfl_down_sync(0xffffffffu, p0, off);
        p1 += __shfl_down_sync(0xffffffffu, p1, off);
    }
    if (lane == 0) {
        const float fb = fcb[0];
        out[b0] = p0 + fb;
        out[b1] = p1 + fb;
    }
}

extern "C" void kernel_launch(void* const* d_in, const int* in_sizes, int n_in,
                              void* d_out, int out_size)
{
    const float* x   = (const float*)d_in[0];
    const float* Wih = (const float*)d_in[1];
    const float* Whh = (const float*)d_in[2];
    const float* bih = (const float*)d_in[3];
    const float* bhh = (const float*)d_in[4];
    const float* fcW = (const float*)d_in[5];
    const float* fcb = (const float*)d_in[6];
    float* out = (float*)d_out;

    rnn_kernel<<<B_SZ / 4, NTHR>>>(x, Wih, Whh, bih, bhh, fcW, fcb, out);
}